// round 10
// baseline (speedup 1.0000x reference)
#include <cuda_runtime.h>
#include <cstdint>

// out = chem @ (Wout @ Wv)^T + (Wout @ bv + bout)   (softmax over singleton == 1)
//
// Quad compute scheme (R7/R9): lane owns float4 quarter q = t&3, partials for
// all 16 outputs (M = 32 f32x2 regs, lane-permuted), 2-round butterfly
// reduce-scatter, lane stores its own quarter (coalesced STG.128).
// NEW: input comes through a 3-stage cp.async.bulk (UBLKCP) smem ring with
// mbarrier complete_tx — the bulk engine keeps 72 KB/CTA in flight, warps
// issue ZERO global loads (LDS.128 from smem instead). Persistent grid.

#define DIMN   16
#define TPT    6                  // float4 tasks per thread per tile
#define TB4    (256 * TPT)        // 1536 float4 per tile
#define TBYTES (TB4 * 16)         // 24576 B per tile
#define STAGES 3
#define NCTA   296                // 2 per SM, persistent

#define OFF_B   0                 // float2 sB[128]  (1024 B)
#define OFF_C   1024              // float2 sC[8]    (64 B)
#define OFF_BAR 1088              // 3 x u64 mbarriers
#define OFF_BUF 2048              // 3 x 24576 B tile ring
#define SMEM_TOTAL (OFF_BUF + STAGES * TBYTES)   // 75776 B

typedef unsigned long long ull;

__device__ __forceinline__ ull dup2f(float v) {
    ull r; asm("mov.b64 %0, {%1, %1};" : "=l"(r) : "f"(v)); return r;
}
__device__ __forceinline__ void unpack2f(ull v, float& lo, float& hi) {
    asm("mov.b64 {%0, %1}, %2;" : "=f"(lo), "=f"(hi) : "l"(v));
}
__device__ __forceinline__ void ffma2(ull& d, ull a, ull b) {
    asm("fma.rn.f32x2 %0, %1, %2, %3;" : "=l"(d) : "l"(a), "l"(b), "l"(d));
}
__device__ __forceinline__ ull mul2(ull a, ull b) {
    ull r; asm("mul.rn.f32x2 %0, %1, %2;" : "=l"(r) : "l"(a), "l"(b)); return r;
}
__device__ __forceinline__ ull add2(ull a, ull b) {
    ull r; asm("add.rn.f32x2 %0, %1, %2;" : "=l"(r) : "l"(a), "l"(b)); return r;
}

__device__ __forceinline__ uint32_t smem_u32(const void* p) {
    uint32_t a;
    asm("{ .reg .u64 tmp; cvta.to.shared.u64 tmp, %1; cvt.u32.u64 %0, tmp; }"
        : "=r"(a) : "l"(p));
    return a;
}
__device__ __forceinline__ void mbar_init(uint32_t mbar, uint32_t count) {
    asm volatile("mbarrier.init.shared.b64 [%0], %1;" :: "r"(mbar), "r"(count) : "memory");
}
__device__ __forceinline__ void mbar_expect_tx(uint32_t mbar, uint32_t bytes) {
    asm volatile("mbarrier.arrive.expect_tx.shared.b64 _, [%0], %1;"
                 :: "r"(mbar), "r"(bytes) : "memory");
}
__device__ __forceinline__ void bulk_g2s(uint32_t dst, const void* src,
                                         uint32_t bytes, uint32_t mbar) {
    asm volatile(
        "cp.async.bulk.shared::cluster.global.mbarrier::complete_tx::bytes "
        "[%0], [%1], %2, [%3];"
        :: "r"(dst), "l"(src), "r"(bytes), "r"(mbar) : "memory");
}
__device__ __forceinline__ void mbar_wait(uint32_t mbar, uint32_t parity) {
    uint32_t done;
    asm volatile(
        "{\n\t.reg .pred p;\n\t"
        "mbarrier.try_wait.parity.acquire.cta.shared::cta.b64 p, [%1], %2;\n\t"
        "selp.b32 %0, 1, 0, p;\n\t}"
        : "=r"(done) : "r"(mbar), "r"(parity) : "memory");
    if (!done) {
        asm volatile(
            "{\n\t.reg .pred P1;\n\t"
            "WL_%=:\n\t"
            "mbarrier.try_wait.parity.acquire.cta.shared::cta.b64 P1, [%0], %1, 0x989680;\n\t"
            "@P1 bra.uni WD_%=;\n\t"
            "bra.uni WL_%=;\n\t"
            "WD_%=:\n\t}"
            :: "r"(mbar), "r"(parity) : "memory");
    }
}

__device__ __forceinline__ void compute_store(const float4* __restrict__ buf,
                                              float4* __restrict__ gout,
                                              int tile, int t, int total4,
                                              const ull Mreg[4][8],
                                              ull cA, ull cB) {
    int base = tile * TB4 + t;
#pragma unroll
    for (int k = 0; k < TPT; k++) {
        float4 v = buf[t + k * 256];           // conflict-free LDS.128

        ull P[8];
        ull xd = dup2f(v.x);
#pragma unroll
        for (int m = 0; m < 8; m++) P[m] = mul2(Mreg[0][m], xd);
        xd = dup2f(v.y);
#pragma unroll
        for (int m = 0; m < 8; m++) ffma2(P[m], Mreg[1][m], xd);
        xd = dup2f(v.z);
#pragma unroll
        for (int m = 0; m < 8; m++) ffma2(P[m], Mreg[2][m], xd);
        xd = dup2f(v.w);
#pragma unroll
        for (int m = 0; m < 8; m++) ffma2(P[m], Mreg[3][m], xd);

        ull A0 = add2(P[0], __shfl_xor_sync(0xffffffffu, P[4], 2));
        ull A1 = add2(P[1], __shfl_xor_sync(0xffffffffu, P[5], 2));
        ull A2 = add2(P[2], __shfl_xor_sync(0xffffffffu, P[6], 2));
        ull A3 = add2(P[3], __shfl_xor_sync(0xffffffffu, P[7], 2));
        ull F0 = add2(A0, __shfl_xor_sync(0xffffffffu, A2, 1));
        ull F1 = add2(A1, __shfl_xor_sync(0xffffffffu, A3, 1));
        F0 = add2(F0, cA);
        F1 = add2(F1, cB);

        int p = base + k * 256;
        if (p < total4) {
            float o0, o1, o2, o3;
            unpack2f(F0, o0, o1);
            unpack2f(F1, o2, o3);
            __stcs(&gout[p], make_float4(o0, o1, o2, o3));
        }
    }
}

__global__ __launch_bounds__(256, 2)
void xattn_kernel(const float4* __restrict__ gin,
                  float4* __restrict__ gout,
                  const float* __restrict__ w_in,
                  const float* __restrict__ b_in,
                  const float* __restrict__ w_out,
                  const float* __restrict__ b_out,
                  int total4, int ntiles) {
    extern __shared__ __align__(16) char smem[];
    float2* sB = (float2*)(smem + OFF_B);   // [i*8+p] = (M[2p][i], M[2p+1][i])
    float2* sC = (float2*)(smem + OFF_C);   // [p] = (c[2p], c[2p+1])
    const uint32_t bar0 = smem_u32(smem + OFF_BAR);

    int t = threadIdx.x;

    // ---- per-CTA weight folding + mbarrier init ----
    if (t < 128) {
        int i = t >> 3, p = t & 7;
        float m0 = 0.f, m1 = 0.f;
#pragma unroll
        for (int k = 0; k < DIMN; k++) {
            float wv = w_in[(2 * DIMN + k) * DIMN + i];   // Wv rows 32..47, col i
            m0 += w_out[(2 * p) * DIMN + k] * wv;
            m1 += w_out[(2 * p + 1) * DIMN + k] * wv;
        }
        sB[t] = make_float2(m0, m1);
        if (i == 0) {
            float c0 = b_out[2 * p], c1 = b_out[2 * p + 1];
#pragma unroll
            for (int k = 0; k < DIMN; k++) {
                float bv = b_in[2 * DIMN + k];
                c0 += w_out[(2 * p) * DIMN + k] * bv;
                c1 += w_out[(2 * p + 1) * DIMN + k] * bv;
            }
            sC[p] = make_float2(c0, c1);
        }
    }
    if (t == 0) {
#pragma unroll
        for (int s = 0; s < STAGES; s++) mbar_init(bar0 + 8 * s, 1);
    }
    __syncthreads();

    const int q = t & 3;                 // my input AND output quarter
    ull Mreg[4][8];
#pragma unroll
    for (int il = 0; il < 4; il++) {
        int i = 4 * q + il;
#pragma unroll
        for (int u = 0; u < 4; u++) {
#pragma unroll
            for (int v = 0; v < 2; v++)
                Mreg[il][2 * u + v] = *(const ull*)&sB[i * 8 + 2 * (q ^ u) + v];
        }
    }
    ull cA = *(const ull*)&sC[2 * q + 0];
    ull cB = *(const ull*)&sC[2 * q + 1];

    const int G = gridDim.x;
    if (blockIdx.x >= ntiles) return;

    // ---- prologue: fill the 3-stage ring ----
    if (t == 0) {
#pragma unroll
        for (int s = 0; s < STAGES; s++) {
            int tile = blockIdx.x + s * G;
            if (tile < ntiles) {
                uint32_t rem = (uint32_t)((total4 - tile * TB4) < TB4
                                          ? (total4 - tile * TB4) : TB4) * 16u;
                mbar_expect_tx(bar0 + 8 * s, rem);
                bulk_g2s((uint32_t)(smem_u32(smem + OFF_BUF) + s * TBYTES),
                         gin + tile * TB4, rem, bar0 + 8 * s);
            }
        }
    }

    int T = blockIdx.x;
    uint32_t ph = 0;
    while (true) {
#pragma unroll
        for (int s = 0; s < STAGES; s++) {
            if (T >= ntiles) return;
            mbar_wait(bar0 + 8 * s, ph);
            compute_store((const float4*)(smem + OFF_BUF + s * TBYTES),
                          gout, T, t, total4, Mreg, cA, cB);
            __syncthreads();             // all lanes done reading stage s
            int nx = T + STAGES * G;
            if (t == 0 && nx < ntiles) {
                uint32_t rem = (uint32_t)((total4 - nx * TB4) < TB4
                                          ? (total4 - nx * TB4) : TB4) * 16u;
                mbar_expect_tx(bar0 + 8 * s, rem);
                bulk_g2s((uint32_t)(smem_u32(smem + OFF_BUF) + s * TBYTES),
                         gin + nx * TB4, rem, bar0 + 8 * s);
            }
            T += G;
        }
        ph ^= 1;
    }
}

extern "C" void kernel_launch(void* const* d_in, const int* in_sizes, int n_in,
                              void* d_out, int out_size) {
    // inputs: 0 fp_16 (unused), 1 chem_16, 2 in_proj_weight, 3 in_proj_bias,
    //         4 out_proj_weight, 5 out_proj_bias
    const float* chem  = (const float*)d_in[1];
    const float* w_in  = (const float*)d_in[2];
    const float* b_in  = (const float*)d_in[3];
    const float* w_out = (const float*)d_in[4];
    const float* b_out = (const float*)d_in[5];

    int total4 = in_sizes[1] / 4;            // float4 count
    int ntiles = (total4 + TB4 - 1) / TB4;
    int blocks = ntiles < NCTA ? ntiles : NCTA;

    static int smem_set = 0;
    if (!smem_set) {
        cudaFuncSetAttribute(xattn_kernel,
                             cudaFuncAttributeMaxDynamicSharedMemorySize,
                             SMEM_TOTAL);
        smem_set = 1;
    }

    xattn_kernel<<<blocks, 256, SMEM_TOTAL>>>((const float4*)chem,
                                              (float4*)d_out,
                                              w_in, b_in, w_out, b_out,
                                              total4, ntiles);
}

// round 11
// speedup vs baseline: 1.2196x; 1.2196x over previous
#include <cuda_runtime.h>

// out = chem @ (Wout @ Wv)^T + (Wout @ bv + bout)   (softmax over singleton == 1)
//
// Quad scheme (R7/R9): lane owns float4 quarter q = t&3; partials for all 16
// outputs from its 4 values (M = 32 f32x2 regs, lane-permuted for const-index
// shfl), 2-round butterfly reduce-scatter -> lane stores its own quarter.
// Persistent grid, FOUR-buffer register pipeline (3 tiles / 48 KB/SM in
// flight). R10 regressions reverted. NEW vs R9: guard-free fast path (exact
// tile divisibility, checked on host), strength-reduced addressing.

#define DIMN 16
#define TPT  2            // float4 tasks per thread per tile
#define TB4  (256 * TPT)  // float4s per tile
#define NCTA 296          // 2 per SM, persistent

typedef unsigned long long ull;

__device__ __forceinline__ ull dup2f(float v) {
    ull r; asm("mov.b64 %0, {%1, %1};" : "=l"(r) : "f"(v)); return r;
}
__device__ __forceinline__ void unpack2f(ull v, float& lo, float& hi) {
    asm("mov.b64 {%0, %1}, %2;" : "=f"(lo), "=f"(hi) : "l"(v));
}
__device__ __forceinline__ void ffma2(ull& d, ull a, ull b) {
    asm("fma.rn.f32x2 %0, %1, %2, %3;" : "=l"(d) : "l"(a), "l"(b), "l"(d));
}
__device__ __forceinline__ ull mul2(ull a, ull b) {
    ull r; asm("mul.rn.f32x2 %0, %1, %2;" : "=l"(r) : "l"(a), "l"(b)); return r;
}
__device__ __forceinline__ ull add2(ull a, ull b) {
    ull r; asm("add.rn.f32x2 %0, %1, %2;" : "=l"(r) : "l"(a), "l"(b)); return r;
}

template <bool GUARD>
__device__ __forceinline__ void load_tile(float4 v[TPT],
                                          const float4* __restrict__ gin,
                                          int base, int live, int total4) {
    if (!live) return;                   // uniform per CTA
#pragma unroll
    for (int k = 0; k < TPT; k++) {
        int p = base + k * 256;
        if (GUARD) {
            v[k] = (p < total4) ? __ldcs(&gin[p])
                                : make_float4(0.f, 0.f, 0.f, 0.f);
        } else {
            v[k] = __ldcs(&gin[p]);
        }
    }
}

template <bool GUARD>
__device__ __forceinline__ void compute_store(const float4 v[TPT],
                                              float4* __restrict__ gout,
                                              int base, int total4,
                                              const ull Mreg[4][8],
                                              ull cA, ull cB) {
#pragma unroll
    for (int k = 0; k < TPT; k++) {
        // Partials for all 16 outputs from my 4 values (depth-4 chains).
        ull P[8];
        ull xd = dup2f(v[k].x);
#pragma unroll
        for (int m = 0; m < 8; m++) P[m] = mul2(Mreg[0][m], xd);
        xd = dup2f(v[k].y);
#pragma unroll
        for (int m = 0; m < 8; m++) ffma2(P[m], Mreg[1][m], xd);
        xd = dup2f(v[k].z);
#pragma unroll
        for (int m = 0; m < 8; m++) ffma2(P[m], Mreg[2][m], xd);
        xd = dup2f(v[k].w);
#pragma unroll
        for (int m = 0; m < 8; m++) ffma2(P[m], Mreg[3][m], xd);

        // Butterfly reduce-scatter across the lane-quad (const offsets).
        ull A0 = add2(P[0], __shfl_xor_sync(0xffffffffu, P[4], 2));
        ull A1 = add2(P[1], __shfl_xor_sync(0xffffffffu, P[5], 2));
        ull A2 = add2(P[2], __shfl_xor_sync(0xffffffffu, P[6], 2));
        ull A3 = add2(P[3], __shfl_xor_sync(0xffffffffu, P[7], 2));
        ull F0 = add2(A0, __shfl_xor_sync(0xffffffffu, A2, 1));
        ull F1 = add2(A1, __shfl_xor_sync(0xffffffffu, A3, 1));
        F0 = add2(F0, cA);
        F1 = add2(F1, cB);

        int p = base + k * 256;
        if (!GUARD || p < total4) {
            float o0, o1, o2, o3;
            unpack2f(F0, o0, o1);
            unpack2f(F1, o2, o3);
            __stcs(&gout[p], make_float4(o0, o1, o2, o3));
        }
    }
}

template <bool GUARD>
__global__ __launch_bounds__(256, 2)
void xattn_kernel(const float4* __restrict__ gin,
                  float4* __restrict__ gout,
                  const float* __restrict__ w_in,
                  const float* __restrict__ b_in,
                  const float* __restrict__ w_out,
                  const float* __restrict__ b_out,
                  int total4, int ntiles) {
    __shared__ __align__(16) float2 sB[128];  // [i*8+p] = (M[2p][i], M[2p+1][i])
    __shared__ float2 sC[8];                  // [p] = (c[2p], c[2p+1])

    int t = threadIdx.x;

    // ---- per-CTA weight folding (no separate setup launch) ----
    if (t < 128) {
        int i = t >> 3, p = t & 7;
        float m0 = 0.f, m1 = 0.f;
#pragma unroll
        for (int k = 0; k < DIMN; k++) {
            float wv = w_in[(2 * DIMN + k) * DIMN + i];   // Wv rows 32..47, col i
            m0 += w_out[(2 * p) * DIMN + k] * wv;
            m1 += w_out[(2 * p + 1) * DIMN + k] * wv;
        }
        sB[t] = make_float2(m0, m1);
        if (i == 0) {
            float c0 = b_out[2 * p], c1 = b_out[2 * p + 1];
#pragma unroll
            for (int k = 0; k < DIMN; k++) {
                float bv = b_in[2 * DIMN + k];
                c0 += w_out[(2 * p) * DIMN + k] * bv;
                c1 += w_out[(2 * p + 1) * DIMN + k] * bv;
            }
            sC[p] = make_float2(c0, c1);
        }
    }
    __syncthreads();

    const int q = t & 3;                 // my input AND output quarter

    // M columns for my quarter, lane-permuted for compile-time shfl indices.
    // Mreg[il][2u+v] = (M[4*(q^u)+2v][4q+il], M[4*(q^u)+2v+1][4q+il])
    ull Mreg[4][8];
#pragma unroll
    for (int il = 0; il < 4; il++) {
        int i = 4 * q + il;
#pragma unroll
        for (int u = 0; u < 4; u++) {
#pragma unroll
            for (int v = 0; v < 2; v++)
                Mreg[il][2 * u + v] = *(const ull*)&sB[i * 8 + 2 * (q ^ u) + v];
        }
    }
    ull cA = *(const ull*)&sC[2 * q + 0];
    ull cB = *(const ull*)&sC[2 * q + 1];

    const int S   = gridDim.x;
    const int ST4 = S * TB4;             // float4 step between my tiles
    int T = blockIdx.x;
    if (T >= ntiles) return;

    int base  = T * TB4 + t;             // base of tile T (compute cursor)
    int baseL = base + 3 * ST4;          // base of tile T+3S (load cursor)

    float4 v0[TPT], v1[TPT], v2[TPT], v3[TPT];

    // Prologue: 3 tiles in flight before first compute.
    load_tile<GUARD>(v0, gin, base,           1,                    total4);
    load_tile<GUARD>(v1, gin, base + ST4,     T + S     < ntiles,   total4);
    load_tile<GUARD>(v2, gin, base + 2 * ST4, T + 2 * S < ntiles,   total4);

    while (true) {
        load_tile<GUARD>(v3, gin, baseL, T + 3 * S < ntiles, total4);
        compute_store<GUARD>(v0, gout, base, total4, Mreg, cA, cB);
        T += S; if (T >= ntiles) return;
        base += ST4; baseL += ST4;

        load_tile<GUARD>(v0, gin, baseL, T + 3 * S < ntiles, total4);
        compute_store<GUARD>(v1, gout, base, total4, Mreg, cA, cB);
        T += S; if (T >= ntiles) return;
        base += ST4; baseL += ST4;

        load_tile<GUARD>(v1, gin, baseL, T + 3 * S < ntiles, total4);
        compute_store<GUARD>(v2, gout, base, total4, Mreg, cA, cB);
        T += S; if (T >= ntiles) return;
        base += ST4; baseL += ST4;

        load_tile<GUARD>(v2, gin, baseL, T + 3 * S < ntiles, total4);
        compute_store<GUARD>(v3, gout, base, total4, Mreg, cA, cB);
        T += S; if (T >= ntiles) return;
        base += ST4; baseL += ST4;
    }
}

extern "C" void kernel_launch(void* const* d_in, const int* in_sizes, int n_in,
                              void* d_out, int out_size) {
    // inputs: 0 fp_16 (unused), 1 chem_16, 2 in_proj_weight, 3 in_proj_bias,
    //         4 out_proj_weight, 5 out_proj_bias
    const float* chem  = (const float*)d_in[1];
    const float* w_in  = (const float*)d_in[2];
    const float* b_in  = (const float*)d_in[3];
    const float* w_out = (const float*)d_in[4];
    const float* b_out = (const float*)d_in[5];

    int total4 = in_sizes[1] / 4;            // float4 count
    int ntiles = (total4 + TB4 - 1) / TB4;
    int blocks = ntiles < NCTA ? ntiles : NCTA;

    if (total4 % TB4 == 0) {
        xattn_kernel<false><<<blocks, 256>>>((const float4*)chem,
                                             (float4*)d_out,
                                             w_in, b_in, w_out, b_out,
                                             total4, ntiles);
    } else {
        xattn_kernel<true><<<blocks, 256>>>((const float4*)chem,
                                            (float4*)d_out,
                                            w_in, b_in, w_out, b_out,
                                            total4, ntiles);
    }
}